// round 4
// baseline (speedup 1.0000x reference)
#include <cuda_runtime.h>

#define Bsz     32
#define Anch    3
#define Hd      160
#define Wd      160
#define NT      512
#define NCLS    3
#define PLANE   (Hd*Wd)            // 25600
#define CH      (Anch*8)           // 24
#define CONF_ELEMS (Bsz*Anch*PLANE)   // 2,457,600
#define CONF_V4 (CONF_ELEMS/4)        // 614,400
#define PLANE_V4 (PLANE/4)            // 6400

#define NBLOCK  1184
#define NTHREAD 256

// accumulators: [0]=conf_sumsq [1]=conf_corr [2]=box_sum [3]=cls_sum [4]=n
__device__ double g_acc[5];
__device__ unsigned int g_done;

__device__ __forceinline__ float sigm(float x) {
    return 1.0f / (1.0f + __expf(-x));
}

__global__ void __launch_bounds__(NTHREAD)
detection_loss_kernel(const float* __restrict__ pred,
                      const float* __restrict__ targets,
                      float* __restrict__ out)
{
    const int tid = blockIdx.x * blockDim.x + threadIdx.x;
    const int nth = gridDim.x * blockDim.x;

    double conf_ss = 0.0, conf_corr = 0.0, box_s = 0.0, cls_s = 0.0, nmask = 0.0;

    // ---- dense pass: sigmoid(conf)^2 over the 3 conf planes per batch ----
    {
        float local = 0.0f;
        for (int v = tid; v < CONF_V4; v += nth) {
            int plane_id = v / PLANE_V4;            // 0..95 = b*3 + a
            int off = v - plane_id * PLANE_V4;
            int b = plane_id / Anch;
            int a = plane_id - b * Anch;
            const float4* p = reinterpret_cast<const float4*>(
                pred + (size_t)(b * CH + a * 8 + 4) * PLANE);
            float4 x = __ldg(&p[off]);
            float s0 = sigm(x.x), s1 = sigm(x.y), s2 = sigm(x.z), s3 = sigm(x.w);
            local += s0*s0 + s1*s1 + s2*s2 + s3*s3;
        }
        conf_ss = (double)local;
    }

    // ---- sparse pass: one work item per (target, anchor) ----
    for (int it = tid; it < NT * Anch; it += nth) {
        int t = it / Anch;
        int a = it - t * Anch;
        float tb = targets[t*6 + 0];
        float tc = targets[t*6 + 1];
        float tx = targets[t*6 + 2];
        float ty = targets[t*6 + 3];
        float tw = targets[t*6 + 4];
        float th = targets[t*6 + 5];
        int b  = (int)tb;
        int c  = (int)tc;
        int gx = (int)(tx * (float)Wd);   // f32 multiply + trunc, matches jax
        int gy = (int)(ty * (float)Hd);
        if (gx >= 0 && gx < Wd && gy >= 0 && gy < Hd && b >= 0 && b < Bsz) {
            const float* base = pred + (size_t)(b * CH + a * 8) * PLANE
                                     + (size_t)gy * Wd + gx;
            float p0 = base[0*PLANE];
            float p1 = base[1*PLANE];
            float p2 = base[2*PLANE];
            float p3 = base[3*PLANE];
            float p4 = base[4*PLANE];
            float p5 = base[5*PLANE];
            float p6 = base[6*PLANE];
            float p7 = base[7*PLANE];

            float bx = sigm(p0) - tx;
            float by = sigm(p1) - ty;
            float bw = __expf(p2) - tw;
            float bh = __expf(p3) - th;
            box_s += (double)(bx*bx + by*by + bw*bw + bh*bh);

            float s4 = sigm(p4);
            conf_corr += (double)(1.0f - 2.0f * s4);   // (s-1)^2 - s^2

            // one-hot class target only when c < NCLS (reference's c_i drop)
            float t0 = (c == 0) ? 1.0f : 0.0f;
            float t1 = (c == 1) ? 1.0f : 0.0f;
            float t2 = (c == 2) ? 1.0f : 0.0f;
            float d0 = sigm(p5) - t0;
            float d1 = sigm(p6) - t1;
            float d2 = sigm(p7) - t2;
            cls_s += (double)(d0*d0 + d1*d1 + d2*d2);

            nmask += 1.0;
        }
    }

    // ---- block reduction (warp shuffle, then shared) ----
    double vals[5] = { conf_ss, conf_corr, box_s, cls_s, nmask };
    #pragma unroll
    for (int o = 16; o > 0; o >>= 1) {
        #pragma unroll
        for (int i = 0; i < 5; i++)
            vals[i] += __shfl_down_sync(0xFFFFFFFFu, vals[i], o);
    }
    __shared__ double sh[5][NTHREAD/32];
    int wid = threadIdx.x >> 5;
    int lid = threadIdx.x & 31;
    if (lid == 0) {
        #pragma unroll
        for (int i = 0; i < 5; i++) sh[i][wid] = vals[i];
    }
    __syncthreads();

    if (threadIdx.x == 0) {
        double tot[5] = {0,0,0,0,0};
        #pragma unroll
        for (int w = 0; w < NTHREAD/32; w++)
            #pragma unroll
            for (int i = 0; i < 5; i++) tot[i] += sh[i][w];
        #pragma unroll
        for (int i = 0; i < 5; i++) atomicAdd(&g_acc[i], tot[i]);
        __threadfence();
        unsigned int old = atomicAdd(&g_done, 1u);
        if (old == gridDim.x - 1) {
            // last block: all other blocks' atomics are globally visible
            double css  = atomicAdd(&g_acc[0], 0.0);
            double corr = atomicAdd(&g_acc[1], 0.0);
            double bs   = atomicAdd(&g_acc[2], 0.0);
            double cs   = atomicAdd(&g_acc[3], 0.0);
            double n    = atomicAdd(&g_acc[4], 0.0);
            double loss_conf = (css + corr) / (double)CONF_ELEMS;
            double loss_box  = bs / (n * 4.0);
            double loss_cls  = cs / (n * (double)NCLS);
            out[0] = (float)(5.0 * loss_box + loss_conf + loss_cls);
            // reset for next graph replay (module-load state is also zero)
            g_acc[0] = 0.0; g_acc[1] = 0.0; g_acc[2] = 0.0;
            g_acc[3] = 0.0; g_acc[4] = 0.0;
            __threadfence();
            g_done = 0u;
        }
    }
}

extern "C" void kernel_launch(void* const* d_in, const int* in_sizes, int n_in,
                              void* d_out, int out_size)
{
    const float* pred    = (const float*)d_in[0];
    const float* targets = (const float*)d_in[1];
    float* out = (float*)d_out;
    detection_loss_kernel<<<NBLOCK, NTHREAD>>>(pred, targets, out);
}

// round 6
// speedup vs baseline: 1.8300x; 1.8300x over previous
#include <cuda_runtime.h>

#define Bsz     32
#define Anch    3
#define Hd      160
#define Wd      160
#define NT      512
#define NCLS    3
#define PLANE   (Hd*Wd)                 // 25600
#define CONF_ELEMS (Bsz*Anch*PLANE)     // 2,457,600
#define CONF_V4 (CONF_ELEMS/4)          // 614,400
#define PLANE_V4 (PLANE/4)              // 6400

#define NBLOCK  296
#define NTHREAD 256
#define NTH     (NBLOCK*NTHREAD)        // 75,776
#define NWARPS  (NTHREAD/32)

// per-block partial sums: [block][0..4] = conf_ss, conf_corr, box, cls, n
__device__ double g_partial[NBLOCK * 5];
__device__ unsigned int g_done;

__device__ __forceinline__ float sigm(float x) {
    return __fdividef(1.0f, 1.0f + __expf(-x));
}

__global__ void __launch_bounds__(NTHREAD)
detection_loss_kernel(const float* __restrict__ pred,
                      const float* __restrict__ targets,
                      float* __restrict__ out)
{
    const int tid = blockIdx.x * NTHREAD + threadIdx.x;

    double acc[5] = {0.0, 0.0, 0.0, 0.0, 0.0};
    // acc[0]=conf_sumsq acc[1]=conf_corr acc[2]=box acc[3]=cls acc[4]=n

    // ---- dense pass: sum sigmoid(conf)^2 over the 96 conf planes ----
    // conf plane for plane_id=b*3+a lives at channel 8*plane_id+4.
    // float4 global index: g = idx + 44800*(idx/6400) + 25600.
    {
        const float4* __restrict__ p4 = reinterpret_cast<const float4*>(pred);
        float4 x[8];
        #pragma unroll
        for (int j = 0; j < 8; j++) {                 // 8*NTH = 606,208 <= CONF_V4
            int idx = tid + j * NTH;
            int plane = idx / PLANE_V4;
            int g = idx + plane * 44800 + 25600;
            x[j] = __ldg(&p4[g]);
        }
        float local = 0.0f;
        #pragma unroll
        for (int j = 0; j < 8; j++) {
            float s0 = sigm(x[j].x), s1 = sigm(x[j].y);
            float s2 = sigm(x[j].z), s3 = sigm(x[j].w);
            local += s0*s0 + s1*s1 + s2*s2 + s3*s3;
        }
        // remainder: CONF_V4 - 8*NTH = 8192 elements
        if (tid < CONF_V4 - 8 * NTH) {
            int idx = tid + 8 * NTH;
            int plane = idx / PLANE_V4;
            int g = idx + plane * 44800 + 25600;
            float4 xr = __ldg(&p4[g]);
            float s0 = sigm(xr.x), s1 = sigm(xr.y);
            float s2 = sigm(xr.z), s3 = sigm(xr.w);
            local += s0*s0 + s1*s1 + s2*s2 + s3*s3;
        }
        acc[0] = (double)local;
    }

    // ---- sparse pass: one item per (target, anchor); NT*Anch = 1536 << NTH ----
    if (tid < NT * Anch) {
        int t = tid / Anch;
        int a = tid - t * Anch;
        float tb = targets[t*6 + 0];
        float tc = targets[t*6 + 1];
        float tx = targets[t*6 + 2];
        float ty = targets[t*6 + 3];
        float tw = targets[t*6 + 4];
        float th = targets[t*6 + 5];
        int b  = (int)tb;
        int c  = (int)tc;
        int gx = (int)(tx * (float)Wd);
        int gy = (int)(ty * (float)Hd);
        if (gx >= 0 && gx < Wd && gy >= 0 && gy < Hd && b >= 0 && b < Bsz) {
            const float* base = pred + (size_t)(b * 24 + a * 8) * PLANE
                                     + (size_t)gy * Wd + gx;
            float p0 = base[0*PLANE];
            float p1 = base[1*PLANE];
            float p2 = base[2*PLANE];
            float p3 = base[3*PLANE];
            float p4v = base[4*PLANE];
            float p5 = base[5*PLANE];
            float p6 = base[6*PLANE];
            float p7 = base[7*PLANE];

            float bx = sigm(p0) - tx;
            float by = sigm(p1) - ty;
            float bw = __expf(p2) - tw;
            float bh = __expf(p3) - th;
            acc[2] = (double)(bx*bx + by*by + bw*bw + bh*bh);

            float s4 = sigm(p4v);
            acc[1] = (double)(1.0f - 2.0f * s4);      // (s-1)^2 - s^2

            float t0 = (c == 0) ? 1.0f : 0.0f;
            float t1 = (c == 1) ? 1.0f : 0.0f;
            float t2 = (c == 2) ? 1.0f : 0.0f;
            float d0 = sigm(p5) - t0;
            float d1 = sigm(p6) - t1;
            float d2 = sigm(p7) - t2;
            acc[3] = (double)(d0*d0 + d1*d1 + d2*d2);

            acc[4] = 1.0;
        }
    }

    // ---- block reduction: warp shuffles, then shared ----
    #pragma unroll
    for (int o = 16; o > 0; o >>= 1)
        #pragma unroll
        for (int i = 0; i < 5; i++)
            acc[i] += __shfl_down_sync(0xFFFFFFFFu, acc[i], o);

    __shared__ double sh[NWARPS][5];
    __shared__ int is_last;
    int wid = threadIdx.x >> 5;
    int lid = threadIdx.x & 31;
    if (lid == 0)
        #pragma unroll
        for (int i = 0; i < 5; i++) sh[wid][i] = acc[i];
    __syncthreads();

    if (threadIdx.x == 0) {
        double tot[5] = {0,0,0,0,0};
        #pragma unroll
        for (int w = 0; w < NWARPS; w++)
            #pragma unroll
            for (int i = 0; i < 5; i++) tot[i] += sh[w][i];
        #pragma unroll
        for (int i = 0; i < 5; i++)
            g_partial[blockIdx.x * 5 + i] = tot[i];
        __threadfence();
        unsigned int old = atomicAdd(&g_done, 1u);
        is_last = (old == (unsigned)(gridDim.x - 1)) ? 1 : 0;
    }
    __syncthreads();

    // ---- last block reduces all partials and finalizes ----
    if (is_last) {
        double fin[5] = {0,0,0,0,0};
        for (int i = threadIdx.x; i < NBLOCK; i += NTHREAD) {
            #pragma unroll
            for (int k = 0; k < 5; k++)
                fin[k] += __ldcg(&g_partial[i * 5 + k]);
        }
        #pragma unroll
        for (int o = 16; o > 0; o >>= 1)
            #pragma unroll
            for (int k = 0; k < 5; k++)
                fin[k] += __shfl_down_sync(0xFFFFFFFFu, fin[k], o);
        if (lid == 0)
            #pragma unroll
            for (int k = 0; k < 5; k++) sh[wid][k] = fin[k];
        __syncthreads();
        if (threadIdx.x == 0) {
            double tot[5] = {0,0,0,0,0};
            #pragma unroll
            for (int w = 0; w < NWARPS; w++)
                #pragma unroll
                for (int k = 0; k < 5; k++) tot[k] += sh[w][k];
            double loss_conf = (tot[0] + tot[1]) / (double)CONF_ELEMS;
            double loss_box  = tot[2] / (tot[4] * 4.0);
            double loss_cls  = tot[3] / (tot[4] * (double)NCLS);
            out[0] = (float)(5.0 * loss_box + loss_conf + loss_cls);
            g_done = 0u;                // reset for next graph replay
        }
    }
}

extern "C" void kernel_launch(void* const* d_in, const int* in_sizes, int n_in,
                              void* d_out, int out_size)
{
    const float* pred    = (const float*)d_in[0];
    const float* targets = (const float*)d_in[1];
    float* out = (float*)d_out;
    detection_loss_kernel<<<NBLOCK, NTHREAD>>>(pred, targets, out);
}